// round 12
// baseline (speedup 1.0000x reference)
#include <cuda_runtime.h>
#include <cuda_bf16.h>

#define FULL 0xffffffffu
typedef unsigned long long u64;

// Packed f32x2 primitives (sm_103a FFMA2 path, PTX-only)
#define MK2(d, lo, hi)   asm("mov.b64 %0, {%1, %2};" : "=l"(d) : "f"(lo), "f"(hi))
#define UP2(lo, hi, s)   asm("mov.b64 {%0, %1}, %2;" : "=f"(lo), "=f"(hi) : "l"(s))
#define PMUL(d, a, b)    asm("mul.rn.f32x2 %0, %1, %2;" : "=l"(d) : "l"(a), "l"(b))
#define PFMA(d, a, b, c) asm("fma.rn.f32x2 %0, %1, %2, %3;" : "=l"(d) : "l"(a), "l"(b), "l"(c))
#define PADD(d, a, b)    asm("add.rn.f32x2 %0, %1, %2;" : "=l"(d) : "l"(a), "l"(b))
#define TANH_APPROX(d, x) asm("tanh.approx.f32 %0, %1;" : "=f"(d) : "f"(x))
#define RCP_APPROX(d, x)  asm("rcp.approx.f32 %0, %1;" : "=f"(d) : "f"(x))

__device__ __forceinline__ u64 paxpby(u64 A, u64 X, u64 B, u64 Y) {
    u64 t, d; PMUL(t, B, Y); PFMA(d, A, X, t); return d;
}
__device__ __forceinline__ u64 dup2(float v) { u64 d; MK2(d, v, v); return d; }

// Layout: 4 batch elements per warp (8 lanes each; element = lane>>3).
// Amplitude index i: bits 0-2 = lane bits, bits 3-7 = register bits.
// Pack slot = amp bit3; pack index j (4 bits) = amp bits 4-7 (srp[16]).
// Qubit q lives on amplitude bit (7-q).
//
// f0 = Z3-signed norm after CRX0..2, f1 = Z7-signed norm after CRX0..6;
// CRX7..9 cancel (exact).  CRX pair gates couple packs in independent
// components {8..15},{4..7},{2,3},{1},{0}; each component is evolved through
// CRX0..6 separately so its imaginary registers live briefly.

__global__ void __launch_bounds__(64)
vqc_kernel(const float* __restrict__ x,         // (B, 4, 8)
           const float* __restrict__ crx_theta, // (10,)
           const float* __restrict__ w1,        // (10, 2)
           const float* __restrict__ b1,        // (10,)
           const float* __restrict__ w2,        // (1, 10)
           const float* __restrict__ b2,        // (1,)
           float* __restrict__ out,             // (B, 1)
           int n_batch) {
    const int warp = (int)((blockIdx.x * blockDim.x + threadIdx.x) >> 5);
    const int lane = threadIdx.x & 31;
    const int e0   = warp * 4;
    if (e0 >= n_batch) return;
    const int gb = lane & 24;      // element group base lane
    const int lo = lane & 7;

    int em = e0 + (lane >> 3);
    int eL = em < n_batch ? em : n_batch - 1;
    const float* xb = x + (size_t)eL * 32;
    float ang[4];
    #pragma unroll
    for (int k = 0; k < 4; k++) ang[k] = xb[lo + k * 8];

    u64 srp[16];

    // ---------------- Cycle 0: closed form ----------------
    {
        float mys, myc;
        __sincosf(0.5f * ang[0], &mys, &myc);
        float cq[8], sq[8];
        #pragma unroll
        for (int q = 0; q < 8; q++) {
            cq[q] = __shfl_sync(FULL, myc, gb | q);
            sq[q] = __shfl_sync(FULL, mys, gb | q);
        }
        const int x0 = lane & 1, x1 = (lane >> 1) & 1, x2 = (lane >> 2) & 1;
        float Lbase = ((x0 ^ x1) ? sq[7] : cq[7]) * ((x1 ^ x2) ? sq[6] : cq[6]);
        float f2_0 = x2 ? sq[5] : cq[5];
        float f2_1 = x2 ? cq[5] : sq[5];
        float f6_0 = x0 ? sq[1] : cq[1];
        float f6_1 = x0 ? cq[1] : sq[1];
        float f7_0 = x0 ? sq[0] : cq[0];
        float f7_1 = x0 ? cq[0] : sq[0];
        float A0 = Lbase * f2_0, A1 = Lbase * f2_1;
        float A00 = A0 * cq[4], A01 = A0 * sq[4];
        float A10 = A1 * sq[4], A11 = A1 * cq[4];
        #pragma unroll
        for (int j = 0; j < 16; j++) {
            const int b4 = j & 1, b5 = (j >> 1) & 1, b6 = (j >> 2) & 1, b7 = (j >> 3) & 1;
            float w = ((b4 ^ b5) ? sq[3] : cq[3])
                    * ((b5 ^ b6) ? sq[2] : cq[2])
                    * ((b6 ^ b7) ? f6_1 : f6_0)
                    * (b7 ? f7_1 : f7_0);
            float l_ = (b4 ? A01 : A00) * w;
            float h_ = (b4 ? A11 : A10) * w;
            MK2(srp[j], l_, h_);
        }
    }

    // ---------------- Cycles 1..3: fused RY+CNOT ----------------
    #pragma unroll
    for (int k = 1; k < 4; k++) {
        float mys, myc;
        __sincosf(0.5f * ang[k], &mys, &myc);
        float c_, s_;
        #define BCAST(q) { c_ = __shfl_sync(FULL, myc, gb | (q)); \
                           s_ = __shfl_sync(FULL, mys, gb | (q)); }

        BCAST(0)
        if (k == 1) {
            u64 CC = dup2(c_), SS = dup2(s_), NS = dup2(-s_);
            #pragma unroll
            for (int j = 0; j < 8; j++) {
                u64 a = srp[j], b = srp[j + 8];
                srp[j]     = paxpby(CC, a, NS, b);
                srp[j + 8] = paxpby(SS, a, CC, b);
            }
        } else {
            bool g = lane & 1;
            u64 AL0 = dup2(g ? -s_ : c_), GA0 = dup2(g ? c_ : -s_);
            u64 AL1 = dup2(g ?  s_ : c_), GA1 = dup2(g ? c_ :  s_);
            #pragma unroll
            for (int j = 0; j < 8; j++) {
                u64 a = srp[j], b = srp[j + 8];
                srp[j]     = paxpby(AL0, a, GA0, b);
                srp[j + 8] = paxpby(AL1, b, GA1, a);
            }
        }
        #define RGATE(DIST, CB) {                                            \
            u64 CC = dup2(c_), SS = dup2(s_), NS = dup2(-s_);                \
            _Pragma("unroll")                                                \
            for (int j = 0; j < 16; j++) {                                   \
                if (!(j & (DIST))) {                                         \
                    const int j2 = j | (DIST);                               \
                    u64 a = srp[j], b = srp[j2];                             \
                    u64 n0 = paxpby(CC, a, NS, b);                           \
                    u64 n1 = paxpby(SS, a, CC, b);                           \
                    if (j & (CB)) { srp[j] = n1; srp[j2] = n0; }             \
                    else          { srp[j] = n0; srp[j2] = n1; }             \
                }                                                            \
            } }
        BCAST(1) RGATE(4, 8)
        BCAST(2) RGATE(2, 4)
        BCAST(3) RGATE(1, 2)
        #undef RGATE
        BCAST(4)
        {
            u64 CC = dup2(c_);
            u64 SV; MK2(SV, -s_, s_);
            u64 SW; MK2(SW, s_, -s_);
            #pragma unroll
            for (int j = 0; j < 16; j++) {
                float a0, a1; UP2(a0, a1, srp[j]);
                u64 rv; MK2(rv, a1, a0);
                if (j & 1) srp[j] = paxpby(CC, rv, SW, srp[j]);
                else       srp[j] = paxpby(CC, srp[j], SV, rv);
            }
        }
        BCAST(5)
        {
            float t = ((lane >> 2) & 1) ? s_ : -s_;
            u64 ALv; MK2(ALv, c_, -t);
            u64 GAv; MK2(GAv, t, c_);
            #pragma unroll
            for (int j = 0; j < 16; j++) {
                u64 p = __shfl_xor_sync(FULL, srp[j], 4);
                srp[j] = paxpby(ALv, srp[j], GAv, p);
            }
        }
        #define LGATE(B) {                                                   \
            float t = ((lane >> (B)) & 1) ? s_ : -s_;                        \
            bool  g = (lane >> ((B) + 1)) & 1;                               \
            u64 AL = dup2(g ? -t : c_);                                      \
            u64 GA = dup2(g ?  c_ : t);                                      \
            _Pragma("unroll")                                                \
            for (int j = 0; j < 16; j++) {                                   \
                u64 p = __shfl_xor_sync(FULL, srp[j], 1 << (B));             \
                srp[j] = paxpby(AL, srp[j], GA, p);                          \
            } }
        BCAST(6) LGATE(1)
        BCAST(7) LGATE(0)
        #undef LGATE
        #undef BCAST
    }
    // Cycle 3's trailing CNOT(0,7): conditional pack swap (j <-> j+8)
    {
        bool g = lane & 1;
        #pragma unroll
        for (int j = 0; j < 8; j++) {
            u64 a = srp[j], b = srp[j + 8];
            srp[j]     = g ? b : a;
            srp[j + 8] = g ? a : b;
        }
    }

    // ---------------- CRX phase, per component ----------------
    float thA = __ldg(&crx_theta[lo]);
    float csnA, ccoA;
    __sincosf(0.5f * thA, &csnA, &ccoA);
    float co0 = __shfl_sync(FULL, ccoA, gb | 0), sn0 = __shfl_sync(FULL, csnA, gb | 0);
    float co1 = __shfl_sync(FULL, ccoA, gb | 1), sn1 = __shfl_sync(FULL, csnA, gb | 1);
    float co2 = __shfl_sync(FULL, ccoA, gb | 2), sn2 = __shfl_sync(FULL, csnA, gb | 2);
    float co3 = __shfl_sync(FULL, ccoA, gb | 3), sn3 = __shfl_sync(FULL, csnA, gb | 3);
    float co4 = __shfl_sync(FULL, ccoA, gb | 4), sn4 = __shfl_sync(FULL, csnA, gb | 4);
    float co5 = __shfl_sync(FULL, ccoA, gb | 5), sn5 = __shfl_sync(FULL, csnA, gb | 5);
    float co6 = __shfl_sync(FULL, ccoA, gb | 6), sn6 = __shfl_sync(FULL, csnA, gb | 6);
    // CRX4: ctrl = slot (amp bit3) -> per-slot packed coeffs, lane-invariant
    u64 CO4, SN4, NSN4;
    MK2(CO4, 1.0f, co4);  MK2(SN4, 0.0f, sn4);  MK2(NSN4, 0.0f, -sn4);
    // CRX5/6: ctrl lane bits folded into scalars
    bool  gl5 = (lane >> 2) & 1;
    float ce5 = gl5 ? co5 : 1.0f, se5 = gl5 ? sn5 : 0.0f;
    bool  gl6 = (lane >> 1) & 1;
    float ce6 = gl6 ? co6 : 1.0f, se6 = gl6 ? sn6 : 0.0f;

    u64 accP, accM, accT;   // f0 plus / f0 minus / f1 total
    { float z0 = 0.0f; MK2(accP, z0, z0); MK2(accM, z0, z0); MK2(accT, z0, z0); }

    #define CRX4_PK(SR, SI) { u64 pr = __shfl_xor_sync(FULL, SR, 4);          \
        u64 pi = __shfl_xor_sync(FULL, SI, 4);                                \
        SR = paxpby(CO4, SR, SN4, pi);  SI = paxpby(CO4, SI, NSN4, pr); }
    #define CRXL_PK(SR, SI, MASK, COe, SNe, NSNe) {                           \
        u64 pr = __shfl_xor_sync(FULL, SR, MASK);                             \
        u64 pi = __shfl_xor_sync(FULL, SI, MASK);                             \
        SR = paxpby(COe, SR, SNe, pi);  SI = paxpby(COe, SI, NSNe, pr); }
    #define F1ACC(SR, SI) { PFMA(accT, SR, SR, accT); PFMA(accT, SI, SI, accT); }
    #define CFULL(AR, AI, BR, BI, CO, SN, NSN) {                              \
        u64 ar = AR, ai = AI, br = BR, bi = BI;                               \
        AR = paxpby(CO, ar, SN,  bi);  AI = paxpby(CO, ai, NSN, br);          \
        BR = paxpby(CO, br, SN,  ai);  BI = paxpby(CO, bi, NSN, ar); }
    #define CRX3_PK(SR, SI, CO, SN, NSN) {                                    \
        float r0, r1, i0, i1;                                                 \
        UP2(r0, r1, SR);  UP2(i0, i1, SI);                                    \
        u64 rvr; MK2(rvr, r1, r0);                                            \
        u64 rvi; MK2(rvi, i1, i0);                                            \
        SR = paxpby(CO, SR, SN,  rvi);  SI = paxpby(CO, SI, NSN, rvr); }

    // ===== Component {8..15} =====
    {
        u64 si8[8];
        { // CRX0 (ctrl bit7 set on these packs): RE pairs (8,12)..(11,15)
          u64 CO = dup2(co0), NSN = dup2(-sn0);
          #pragma unroll
          for (int t = 0; t < 4; t++) {
              u64 a = srp[8 + t], b = srp[12 + t];
              PMUL(srp[8 + t],  CO,  a);  PMUL(si8[t],     NSN, b);
              PMUL(srp[12 + t], CO,  b);  PMUL(si8[4 + t], NSN, a);
          } }
        { // CRX1 FULL pairs (12,14),(13,15)
          u64 CO = dup2(co1), SN = dup2(sn1), NSN = dup2(-sn1);
          #pragma unroll
          for (int t = 0; t < 2; t++)
              CFULL(srp[12 + t], si8[4 + t], srp[14 + t], si8[6 + t], CO, SN, NSN)
        }
        { // CRX2 FULL pairs (10,11),(14,15)
          u64 CO = dup2(co2), SN = dup2(sn2), NSN = dup2(-sn2);
          CFULL(srp[10], si8[2], srp[11], si8[3], CO, SN, NSN)
          CFULL(srp[14], si8[6], srp[15], si8[7], CO, SN, NSN)
        }
        // f0 partial (post-CRX2): even packs -> P, odd -> M
        #pragma unroll
        for (int t = 0; t < 8; t += 2) {
            PFMA(accP, srp[8 + t], srp[8 + t], accP);  PFMA(accP, si8[t],     si8[t],     accP);
            PFMA(accM, srp[9 + t], srp[9 + t], accM);  PFMA(accM, si8[t + 1], si8[t + 1], accM);
        }
        { // CRX3 on odd packs 9,11,13,15
          u64 CO = dup2(co3), SN = dup2(sn3), NSN = dup2(-sn3);
          #pragma unroll
          for (int t = 1; t < 8; t += 2) CRX3_PK(srp[8 + t], si8[t], CO, SN, NSN)
        }
        #pragma unroll
        for (int t = 0; t < 8; t++) CRX4_PK(srp[8 + t], si8[t])
        { u64 CO5 = dup2(ce5), SN5 = dup2(se5), NSN5 = dup2(-se5);
          #pragma unroll
          for (int t = 0; t < 8; t++) CRXL_PK(srp[8 + t], si8[t], 2, CO5, SN5, NSN5) }
        { u64 CO6 = dup2(ce6), SN6 = dup2(se6), NSN6 = dup2(-se6);
          #pragma unroll
          for (int t = 0; t < 8; t++) CRXL_PK(srp[8 + t], si8[t], 1, CO6, SN6, NSN6) }
        #pragma unroll
        for (int t = 0; t < 8; t++) F1ACC(srp[8 + t], si8[t])
    }

    // ===== Component {4..7} =====
    {
        u64 si4[4];
        { // CRX1 (ctrl bit6 set): RE pairs (4,6),(5,7)
          u64 CO = dup2(co1), NSN = dup2(-sn1);
          #pragma unroll
          for (int t = 0; t < 2; t++) {
              u64 a = srp[4 + t], b = srp[6 + t];
              PMUL(srp[4 + t], CO,  a);  PMUL(si4[t],     NSN, b);
              PMUL(srp[6 + t], CO,  b);  PMUL(si4[2 + t], NSN, a);
          } }
        { // CRX2 FULL pair (6,7)
          u64 CO = dup2(co2), SN = dup2(sn2), NSN = dup2(-sn2);
          CFULL(srp[6], si4[2], srp[7], si4[3], CO, SN, NSN)
        }
        PFMA(accP, srp[4], srp[4], accP);  PFMA(accP, si4[0], si4[0], accP);
        PFMA(accM, srp[5], srp[5], accM);  PFMA(accM, si4[1], si4[1], accM);
        PFMA(accP, srp[6], srp[6], accP);  PFMA(accP, si4[2], si4[2], accP);
        PFMA(accM, srp[7], srp[7], accM);  PFMA(accM, si4[3], si4[3], accM);
        { u64 CO = dup2(co3), SN = dup2(sn3), NSN = dup2(-sn3);
          CRX3_PK(srp[5], si4[1], CO, SN, NSN)
          CRX3_PK(srp[7], si4[3], CO, SN, NSN) }
        #pragma unroll
        for (int t = 0; t < 4; t++) CRX4_PK(srp[4 + t], si4[t])
        { u64 CO5 = dup2(ce5), SN5 = dup2(se5), NSN5 = dup2(-se5);
          #pragma unroll
          for (int t = 0; t < 4; t++) CRXL_PK(srp[4 + t], si4[t], 2, CO5, SN5, NSN5) }
        { u64 CO6 = dup2(ce6), SN6 = dup2(se6), NSN6 = dup2(-se6);
          #pragma unroll
          for (int t = 0; t < 4; t++) CRXL_PK(srp[4 + t], si4[t], 1, CO6, SN6, NSN6) }
        #pragma unroll
        for (int t = 0; t < 4; t++) F1ACC(srp[4 + t], si4[t])
    }

    // ===== Component {2,3} =====
    {
        u64 si2[2];
        { // CRX2 (ctrl bit5 set): RE pair (2,3)
          u64 CO = dup2(co2), NSN = dup2(-sn2);
          u64 a = srp[2], b = srp[3];
          PMUL(srp[2], CO, a);  PMUL(si2[0], NSN, b);
          PMUL(srp[3], CO, b);  PMUL(si2[1], NSN, a); }
        PFMA(accP, srp[2], srp[2], accP);  PFMA(accP, si2[0], si2[0], accP);
        PFMA(accM, srp[3], srp[3], accM);  PFMA(accM, si2[1], si2[1], accM);
        { u64 CO = dup2(co3), SN = dup2(sn3), NSN = dup2(-sn3);
          CRX3_PK(srp[3], si2[1], CO, SN, NSN) }
        #pragma unroll
        for (int t = 0; t < 2; t++) CRX4_PK(srp[2 + t], si2[t])
        { u64 CO5 = dup2(ce5), SN5 = dup2(se5), NSN5 = dup2(-se5);
          #pragma unroll
          for (int t = 0; t < 2; t++) CRXL_PK(srp[2 + t], si2[t], 2, CO5, SN5, NSN5) }
        { u64 CO6 = dup2(ce6), SN6 = dup2(se6), NSN6 = dup2(-se6);
          #pragma unroll
          for (int t = 0; t < 2; t++) CRXL_PK(srp[2 + t], si2[t], 1, CO6, SN6, NSN6) }
        F1ACC(srp[2], si2[0])
        F1ACC(srp[3], si2[1])
    }

    // ===== Component {1} =====
    {
        PFMA(accM, srp[1], srp[1], accM);   // f0 (still real, odd pack)
        u64 si1;
        { // CRX3 RE (pack 1, within-pack reversed)
          u64 CO = dup2(co3), NSN = dup2(-sn3);
          float a0, a1; UP2(a0, a1, srp[1]);
          u64 rv; MK2(rv, a1, a0);
          PMUL(srp[1], CO, srp[1]);
          PMUL(si1, NSN, rv); }
        CRX4_PK(srp[1], si1)
        { u64 CO5 = dup2(ce5), SN5 = dup2(se5), NSN5 = dup2(-se5);
          CRXL_PK(srp[1], si1, 2, CO5, SN5, NSN5) }
        { u64 CO6 = dup2(ce6), SN6 = dup2(se6), NSN6 = dup2(-se6);
          CRXL_PK(srp[1], si1, 1, CO6, SN6, NSN6) }
        F1ACC(srp[1], si1)
    }

    // ===== Component {0} =====
    {
        PFMA(accP, srp[0], srp[0], accP);   // f0 (real, even pack)
        u64 si0;
        { // CRX4 with si==0: only srp shuffle needed
          u64 pr = __shfl_xor_sync(FULL, srp[0], 4);
          u64 t0 = srp[0];
          PMUL(srp[0], CO4, t0);
          PMUL(si0, NSN4, pr); }
        { u64 CO5 = dup2(ce5), SN5 = dup2(se5), NSN5 = dup2(-se5);
          CRXL_PK(srp[0], si0, 2, CO5, SN5, NSN5) }
        { u64 CO6 = dup2(ce6), SN6 = dup2(se6), NSN6 = dup2(-se6);
          CRXL_PK(srp[0], si0, 1, CO6, SN6, NSN6) }
        F1ACC(srp[0], si0)
    }

    #undef CRX4_PK
    #undef CRXL_PK
    #undef F1ACC
    #undef CFULL
    #undef CRX3_PK

    // ---------------- Combine + reduction + MLP ----------------
    float p0, p1, m0, m1, t0, t1;
    UP2(p0, p1, accP);  UP2(m0, m1, accM);  UP2(t0, t1, accT);
    float f0p = (p0 + p1) - (m0 + m1);
    float T   = t0 + t1;
    float f1p = (lane & 1) ? -T : T;

    float f0, f1;
    u64 fv; MK2(fv, f0p, f1p);
    #pragma unroll
    for (int m = 4; m >= 1; m >>= 1) {
        u64 p = __shfl_xor_sync(FULL, fv, m);
        PADD(fv, fv, p);
    }
    UP2(f0, f1, fv);

    // Hidden units: lane lo handles unit lo; lanes 0,1 also units 8,9.
    float z1 = fmaf(f0, __ldg(&w1[lo * 2 + 0]),
               fmaf(f1, __ldg(&w1[lo * 2 + 1]), __ldg(&b1[lo])));
    float h1; TANH_APPROX(h1, z1);
    float contrib = h1 * __ldg(&w2[lo]);
    if (lo < 2) {
        const int u = 8 + lo;
        float z2 = fmaf(f0, __ldg(&w1[u * 2 + 0]),
                   fmaf(f1, __ldg(&w1[u * 2 + 1]), __ldg(&b1[u])));
        float h2; TANH_APPROX(h2, z2);
        contrib = fmaf(h2, __ldg(&w2[u]), contrib);
    }
    #pragma unroll
    for (int m = 4; m >= 1; m >>= 1)
        contrib += __shfl_xor_sync(FULL, contrib, m);

    if (lo == 0 && em < n_batch) {
        float z = contrib + __ldg(&b2[0]);
        float den = 1.0f + __expf(-z);
        float r; RCP_APPROX(r, den);
        out[em] = r;
    }
}

extern "C" void kernel_launch(void* const* d_in, const int* in_sizes, int n_in,
                              void* d_out, int out_size) {
    const float* x         = (const float*)d_in[0];
    const float* crx_theta = (const float*)d_in[1];
    const float* w1        = (const float*)d_in[2];
    const float* b1        = (const float*)d_in[3];
    const float* w2        = (const float*)d_in[4];
    const float* b2        = (const float*)d_in[5];
    float* out = (float*)d_out;

    const int n_batch = in_sizes[0] / 32;            // (B,4,8) -> B
    const int nwarps  = (n_batch + 3) / 4;           // 4 elements per warp
    const int threads = 64;                          // 2 warps per block
    const int blocks  = (nwarps + 1) / 2;
    vqc_kernel<<<blocks, threads>>>(x, crx_theta, w1, b1, w2, b2, out, n_batch);
}